// round 11
// baseline (speedup 1.0000x reference)
#include <cuda_runtime.h>
#include <cuda_bf16.h>
#include <cstdint>
#include <cstddef>

// ---------------- problem constants ----------------
#define B_ROWS 4096
#define C_ROWS 65536
#define DIM    1024
#define TOPK   5

// ---------------- GEMM tiling (proven R2/R10 config) ----------------
#define BM 128
#define BN 128
#define BK 32
#define NTILES (C_ROWS / BN)          // 512
#define CAND_PER_TILE 8
#define CAND_PER_ROW (NTILES * CAND_PER_TILE)  // 4096
#define RESCORE 16

#define SROW 40
#define STAGE_BYTES (2 * BM * SROW * 2)        // 20480
#define CS_STRIDE 129
#define SMEM_BYTES (BM * CS_STRIDE * 4)        // 66048

// ---------------- device scratch ----------------
__device__ __align__(16) __nv_bfloat16 g_memb[(size_t)C_ROWS * DIM]; // normalized bf16
__device__ __align__(16) __nv_bfloat16 g_xb[(size_t)B_ROWS * DIM];   // raw bf16
__device__ float g_minv[C_ROWS];
__device__ float g_xinv[B_ROWS];
__device__ __align__(16) float g_cv[(size_t)B_ROWS * CAND_PER_ROW];
__device__ __align__(16) int   g_ci[(size_t)B_ROWS * CAND_PER_ROW];

// ---------------- PTX helpers ----------------
__device__ __forceinline__ void cp16(uint32_t saddr, const void* gaddr) {
    asm volatile("cp.async.cg.shared.global [%0], [%1], 16;" :: "r"(saddr), "l"(gaddr));
}
__device__ __forceinline__ void cp_commit() {
    asm volatile("cp.async.commit_group;" ::: "memory");
}
__device__ __forceinline__ void ldsm4(uint32_t (&r)[4], uint32_t addr) {
    asm volatile("ldmatrix.sync.aligned.m8n8.x4.shared.b16 {%0,%1,%2,%3}, [%4];"
                 : "=r"(r[0]), "=r"(r[1]), "=r"(r[2]), "=r"(r[3]) : "r"(addr));
}
__device__ __forceinline__ void mma16816(float (&c)[4], const uint32_t (&a)[4],
                                         uint32_t b0, uint32_t b1) {
    asm volatile(
        "mma.sync.aligned.m16n8k16.row.col.f32.bf16.bf16.f32 "
        "{%0,%1,%2,%3},{%4,%5,%6,%7},{%8,%9},{%0,%1,%2,%3};"
        : "+f"(c[0]), "+f"(c[1]), "+f"(c[2]), "+f"(c[3])
        : "r"(a[0]), "r"(a[1]), "r"(a[2]), "r"(a[3]), "r"(b0), "r"(b1));
}

// ---------------- fused prep: warp-per-row (measured 56us, 84% HBM) ----------------
__global__ __launch_bounds__(256) void prep_all_kernel(const float* __restrict__ mem,
                                                       const float* __restrict__ x) {
    const int gw = blockIdx.x * 8 + (threadIdx.x >> 5);
    const int lane = threadIdx.x & 31;
    const bool is_mem = (gw < C_ROWS);
    const int row = is_mem ? gw : gw - C_ROWS;
    if (!is_mem && row >= B_ROWS) return;

    const float* src = is_mem ? (mem + (size_t)row * DIM) : (x + (size_t)row * DIM);
    const float4* s4 = reinterpret_cast<const float4*>(src);

    float4 v[8];
    float ss = 0.f;
    #pragma unroll
    for (int j = 0; j < 8; j++) {
        v[j] = s4[lane + 32 * j];
        ss += v[j].x * v[j].x + v[j].y * v[j].y + v[j].z * v[j].z + v[j].w * v[j].w;
    }
    #pragma unroll
    for (int o = 16; o; o >>= 1) ss += __shfl_xor_sync(0xffffffffu, ss, o);
    float iv = 1.0f / fmaxf(sqrtf(ss), 1e-12f);
    if (lane == 0) {
        if (is_mem) g_minv[row] = iv;
        else        g_xinv[row] = iv;
    }
    float sc = is_mem ? iv : 1.0f;   // fold inv-norm into memory only
    __nv_bfloat16* dst = (is_mem ? g_memb : g_xb) + (size_t)row * DIM;
    uint2* d2 = reinterpret_cast<uint2*>(dst);
    #pragma unroll
    for (int j = 0; j < 8; j++) {
        __nv_bfloat162 p0 = __floats2bfloat162_rn(v[j].x * sc, v[j].y * sc);
        __nv_bfloat162 p1 = __floats2bfloat162_rn(v[j].z * sc, v[j].w * sc);
        uint2 w;
        w.x = *reinterpret_cast<uint32_t*>(&p0);
        w.y = *reinterpret_cast<uint32_t*>(&p1);
        d2[lane + 32 * j] = w;
    }
}

// ---------------- coarse GEMM (bf16 HMMA, proven) + per-tile top-8 ----------------
__global__ __launch_bounds__(256) void gemm_topk_kernel() {
    extern __shared__ char smem[];
    const int tid = threadIdx.x;
    const int bm = blockIdx.x;   // fast dim -> consecutive CTAs share B tile in L2
    const int bn = blockIdx.y;
    const uint32_t smem_u = (uint32_t)__cvta_generic_to_shared(smem);

    const int r0 = tid >> 2;
    const int ch = tid & 3;
    const __nv_bfloat16* gA0 = g_xb   + ((size_t)(bm * BM + r0)      * DIM + ch * 8);
    const __nv_bfloat16* gA1 = g_xb   + ((size_t)(bm * BM + r0 + 64) * DIM + ch * 8);
    const __nv_bfloat16* gB0 = g_memb + ((size_t)(bn * BN + r0)      * DIM + ch * 8);
    const __nv_bfloat16* gB1 = g_memb + ((size_t)(bn * BN + r0 + 64) * DIM + ch * 8);

    const uint32_t sa0 = (r0 * SROW + ch * 8) * 2;
    const uint32_t sa1 = ((r0 + 64) * SROW + ch * 8) * 2;

    float acc[4][4][4];
    #pragma unroll
    for (int i = 0; i < 4; i++)
        #pragma unroll
        for (int j = 0; j < 4; j++)
            #pragma unroll
            for (int q = 0; q < 4; q++) acc[i][j][q] = 0.f;

    const int lane = tid & 31;
    const int wm = ((tid >> 5) & 1) * 64;
    const int wn = (tid >> 6) * 32;

    {
        uint32_t base = smem_u;
        cp16(base + sa0, gA0);
        cp16(base + sa1, gA1);
        cp16(base + BM * SROW * 2 + sa0, gB0);
        cp16(base + BM * SROW * 2 + sa1, gB1);
        cp_commit();
    }

    const int NK = DIM / BK;  // 32
    for (int it = 0; it < NK; ++it) {
        if (it + 1 < NK) {
            uint32_t base = smem_u + ((it + 1) & 1) * STAGE_BYTES;
            size_t koff = (size_t)(it + 1) * BK;
            cp16(base + sa0, gA0 + koff);
            cp16(base + sa1, gA1 + koff);
            cp16(base + BM * SROW * 2 + sa0, gB0 + koff);
            cp16(base + BM * SROW * 2 + sa1, gB1 + koff);
            cp_commit();
            asm volatile("cp.async.wait_group 1;");
        } else {
            asm volatile("cp.async.wait_group 0;");
        }
        __syncthreads();

        uint32_t abase = smem_u + (it & 1) * STAGE_BYTES;
        uint32_t bbase = abase + BM * SROW * 2;
        #pragma unroll
        for (int kb = 0; kb < 2; ++kb) {
            uint32_t a[4][4];
            #pragma unroll
            for (int mi = 0; mi < 4; ++mi) {
                uint32_t ad = abase +
                    ((wm + mi * 16 + (lane & 15)) * SROW + kb * 16 + (lane >> 4) * 8) * 2;
                ldsm4(a[mi], ad);
            }
            uint32_t bfr[4][2];
            #pragma unroll
            for (int bp = 0; bp < 2; ++bp) {
                int mat = lane >> 3;
                uint32_t bd = bbase +
                    ((wn + bp * 16 + (mat >> 1) * 8 + (lane & 7)) * SROW +
                     kb * 16 + (mat & 1) * 8) * 2;
                uint32_t r[4];
                ldsm4(r, bd);
                bfr[bp * 2 + 0][0] = r[0]; bfr[bp * 2 + 0][1] = r[1];
                bfr[bp * 2 + 1][0] = r[2]; bfr[bp * 2 + 1][1] = r[3];
            }
            #pragma unroll
            for (int mi = 0; mi < 4; ++mi)
                #pragma unroll
                for (int ni = 0; ni < 4; ++ni)
                    mma16816(acc[mi][ni], a[mi], bfr[ni][0], bfr[ni][1]);
        }
        __syncthreads();
    }

    // epilogue: dump sims to smem, per-row top-8
    float* Cs = reinterpret_cast<float*>(smem);
    #pragma unroll
    for (int mi = 0; mi < 4; ++mi) {
        #pragma unroll
        for (int ni = 0; ni < 4; ++ni) {
            int rb = wm + mi * 16 + (lane >> 2);
            int cb = wn + ni * 8 + (lane & 3) * 2;
            Cs[rb * CS_STRIDE + cb]             = acc[mi][ni][0];
            Cs[rb * CS_STRIDE + cb + 1]         = acc[mi][ni][1];
            Cs[(rb + 8) * CS_STRIDE + cb]       = acc[mi][ni][2];
            Cs[(rb + 8) * CS_STRIDE + cb + 1]   = acc[mi][ni][3];
        }
    }
    __syncthreads();

    if (tid < BM) {
        const float* rowp = Cs + tid * CS_STRIDE;
        float tv[CAND_PER_TILE];
        int   tc[CAND_PER_TILE];
        #pragma unroll
        for (int i = 0; i < CAND_PER_TILE; i++) { tv[i] = -1e30f; tc[i] = 0; }
        for (int c = 0; c < BN; ++c) {
            float v = rowp[c];
            if (v > tv[CAND_PER_TILE - 1]) {
                int p = CAND_PER_TILE - 1;
                while (p > 0 && v > tv[p - 1]) { tv[p] = tv[p - 1]; tc[p] = tc[p - 1]; --p; }
                tv[p] = v; tc[p] = c;
            }
        }
        size_t base = ((size_t)(bm * BM + tid) * NTILES + bn) * CAND_PER_TILE;
        #pragma unroll
        for (int i = 0; i < CAND_PER_TILE; i++) {
            g_cv[base + i] = tv[i];
            g_ci[base + i] = bn * BN + tc[i];
        }
    }
}

// ---------------- phase 2: warp-parallel top-16, exact rescore, softmax, gather ----------------
__global__ __launch_bounds__(256) void rescore_out_kernel(const float* __restrict__ x,
                                                          const float* __restrict__ mem,
                                                          float* __restrict__ out) {
    const int row = blockIdx.x;
    const int tid = threadIdx.x, lane = tid & 31, warp = tid >> 5;  // 8 warps
    __shared__ float wval[128];
    __shared__ int   widx[128];
    __shared__ int   cpos[RESCORE];
    __shared__ float ev[RESCORE];
    __shared__ int   em[RESCORE];
    __shared__ float wgt[TOPK];
    __shared__ int   sidx[TOPK];

    // 1) each warp: coalesced register load of its 512 candidates, local top-16
    {
        const float* cvr = g_cv + (size_t)row * CAND_PER_ROW + warp * 512;
        float lv[16];
        #pragma unroll
        for (int j = 0; j < 16; j++) lv[j] = cvr[lane + 32 * j];

        for (int i = 0; i < RESCORE; ++i) {
            float best = -1e30f; int bj = 0;
            #pragma unroll
            for (int j = 0; j < 16; j++)
                if (lv[j] > best) { best = lv[j]; bj = j; }
            float bv = best; int bl = lane, bjj = bj;
            #pragma unroll
            for (int o = 16; o; o >>= 1) {
                float ov = __shfl_down_sync(0xffffffffu, bv, o);
                int   ol = __shfl_down_sync(0xffffffffu, bl, o);
                int   oj = __shfl_down_sync(0xffffffffu, bjj, o);
                if (ov > bv) { bv = ov; bl = ol; bjj = oj; }
            }
            bv  = __shfl_sync(0xffffffffu, bv, 0);
            bl  = __shfl_sync(0xffffffffu, bl, 0);
            bjj = __shfl_sync(0xffffffffu, bjj, 0);
            if (lane == bl) {
                #pragma unroll
                for (int j = 0; j < 16; j++)
                    if (j == bjj) lv[j] = -1e30f;
            }
            if (lane == 0) {
                wval[warp * 16 + i] = bv;
                widx[warp * 16 + i] = warp * 512 + bl + 32 * bjj;
            }
        }
    }
    __syncthreads();

    // 2) warp 0 merges 128 finalists -> global top-16 positions
    if (warp == 0) {
        float mv[4]; int mi4[4];
        #pragma unroll
        for (int k = 0; k < 4; k++) {
            int p = lane + 32 * k;
            mv[k] = wval[p];
            mi4[k] = widx[p];
        }
        for (int i = 0; i < RESCORE; ++i) {
            float best = -1e30f; int bk = 0;
            #pragma unroll
            for (int k = 0; k < 4; k++)
                if (mv[k] > best) { best = mv[k]; bk = k; }
            float bv = best; int bl = lane, bkk = bk;
            #pragma unroll
            for (int o = 16; o; o >>= 1) {
                float ov = __shfl_down_sync(0xffffffffu, bv, o);
                int   ol = __shfl_down_sync(0xffffffffu, bl, o);
                int   ok = __shfl_down_sync(0xffffffffu, bkk, o);
                if (ov > bv) { bv = ov; bl = ol; bkk = ok; }
            }
            bl  = __shfl_sync(0xffffffffu, bl, 0);
            bkk = __shfl_sync(0xffffffffu, bkk, 0);
            if (lane == bl) {
                cpos[i] = mi4[bkk];
                #pragma unroll
                for (int k = 0; k < 4; k++)
                    if (k == bkk) mv[k] = -1e30f;
            }
        }
    }
    __syncthreads();

    // 3) exact fp32 rescore of 16 candidates (2 per warp)
    const float4* xr = reinterpret_cast<const float4*>(x + (size_t)row * DIM);
    for (int i = warp; i < RESCORE; i += 8) {
        int mi = g_ci[(size_t)row * CAND_PER_ROW + cpos[i]];
        const float4* mr = reinterpret_cast<const float4*>(mem + (size_t)mi * DIM);
        float s = 0.f;
        #pragma unroll
        for (int j = 0; j < 8; j++) {
            float4 a = xr[lane + 32 * j], b = mr[lane + 32 * j];
            s += a.x * b.x + a.y * b.y + a.z * b.z + a.w * b.w;
        }
        #pragma unroll
        for (int o = 16; o; o >>= 1) s += __shfl_down_sync(0xffffffffu, s, o);
        if (lane == 0) { ev[i] = s * g_minv[mi] * g_xinv[row]; em[i] = mi; }
    }
    __syncthreads();

    // 4) top-5, softmax weights
    if (tid == 0) {
        bool used[RESCORE];
        #pragma unroll
        for (int i = 0; i < RESCORE; i++) used[i] = false;
        float tv[TOPK]; int ti[TOPK];
        #pragma unroll
        for (int r = 0; r < TOPK; ++r) {
            float bb = -1e30f; int pp = 0;
            for (int i = 0; i < RESCORE; i++)
                if (!used[i] && ev[i] > bb) { bb = ev[i]; pp = i; }
            used[pp] = true; tv[r] = bb; ti[r] = pp;
        }
        float mx = tv[0];
        float e[TOPK], se = 0.f;
        #pragma unroll
        for (int i = 0; i < TOPK; i++) { e[i] = expf(tv[i] - mx); se += e[i]; }
        #pragma unroll
        for (int i = 0; i < TOPK; i++) { wgt[i] = e[i] / se; sidx[i] = em[ti[i]]; }
    }
    __syncthreads();

    // 5) weighted gather of raw memory rows
    float4 accv = make_float4(0.f, 0.f, 0.f, 0.f);
    #pragma unroll
    for (int i = 0; i < TOPK; i++) {
        const float4* mr = reinterpret_cast<const float4*>(mem + (size_t)sidx[i] * DIM);
        float4 m = mr[tid];
        float wg = wgt[i];
        accv.x += wg * m.x; accv.y += wg * m.y; accv.z += wg * m.z; accv.w += wg * m.w;
    }
    reinterpret_cast<float4*>(out + (size_t)row * DIM)[tid] = accv;
}

// ---------------- launch ----------------
extern "C" void kernel_launch(void* const* d_in, const int* in_sizes, int n_in,
                              void* d_out, int out_size) {
    const float* x   = (const float*)d_in[0];
    const float* mem = (const float*)d_in[1];
    float* out = (float*)d_out;

    cudaFuncSetAttribute(gemm_topk_kernel,
                         cudaFuncAttributeMaxDynamicSharedMemorySize, SMEM_BYTES);

    prep_all_kernel<<<(C_ROWS + B_ROWS) / 8, 256>>>(mem, x);
    gemm_topk_kernel<<<dim3(B_ROWS / BM, NTILES), 256, SMEM_BYTES>>>();
    rescore_out_kernel<<<B_ROWS, 256>>>(x, mem, out);
}

// round 12
// speedup vs baseline: 1.0037x; 1.0037x over previous
#include <cuda_runtime.h>
#include <cuda_bf16.h>
#include <cstdint>
#include <cstddef>

// ---------------- problem constants ----------------
#define B_ROWS 4096
#define C_ROWS 65536
#define DIM    1024
#define TOPK   5

// ---------------- GEMM tiling (proven R2/R10 config) ----------------
#define BM 128
#define BN 128
#define BK 32
#define NTILES (C_ROWS / BN)          // 512
#define CAND_PER_TILE 8
#define CAND_PER_ROW (NTILES * CAND_PER_TILE)  // 4096
#define RESCORE 16

#define SROW 40
#define STAGE_BYTES (2 * BM * SROW * 2)        // 20480
#define CS_STRIDE 129
#define SMEM_BYTES (BM * CS_STRIDE * 4)        // 66048

// ---------------- device scratch ----------------
__device__ __align__(16) __nv_bfloat16 g_memb[(size_t)C_ROWS * DIM]; // normalized bf16
__device__ __align__(16) __nv_bfloat16 g_xb[(size_t)B_ROWS * DIM];   // raw bf16
__device__ float g_minv[C_ROWS];
__device__ float g_xinv[B_ROWS];
__device__ __align__(16) float g_cv[(size_t)B_ROWS * CAND_PER_ROW];
__device__ __align__(16) int   g_ci[(size_t)B_ROWS * CAND_PER_ROW];

// ---------------- PTX helpers ----------------
__device__ __forceinline__ void cp16(uint32_t saddr, const void* gaddr) {
    asm volatile("cp.async.cg.shared.global [%0], [%1], 16;" :: "r"(saddr), "l"(gaddr));
}
__device__ __forceinline__ void cp_commit() {
    asm volatile("cp.async.commit_group;" ::: "memory");
}
__device__ __forceinline__ void ldsm4(uint32_t (&r)[4], uint32_t addr) {
    asm volatile("ldmatrix.sync.aligned.m8n8.x4.shared.b16 {%0,%1,%2,%3}, [%4];"
                 : "=r"(r[0]), "=r"(r[1]), "=r"(r[2]), "=r"(r[3]) : "r"(addr));
}
__device__ __forceinline__ void mma16816(float (&c)[4], const uint32_t (&a)[4],
                                         uint32_t b0, uint32_t b1) {
    asm volatile(
        "mma.sync.aligned.m16n8k16.row.col.f32.bf16.bf16.f32 "
        "{%0,%1,%2,%3},{%4,%5,%6,%7},{%8,%9},{%0,%1,%2,%3};"
        : "+f"(c[0]), "+f"(c[1]), "+f"(c[2]), "+f"(c[3])
        : "r"(a[0]), "r"(a[1]), "r"(a[2]), "r"(a[3]), "r"(b0), "r"(b1));
}

// ---------------- fused prep: warp-per-row (measured 56us, 84% HBM) ----------------
__global__ __launch_bounds__(256) void prep_all_kernel(const float* __restrict__ mem,
                                                       const float* __restrict__ x) {
    const int gw = blockIdx.x * 8 + (threadIdx.x >> 5);   // global warp id
    const int lane = threadIdx.x & 31;
    const bool is_mem = (gw < C_ROWS);
    const int row = is_mem ? gw : gw - C_ROWS;
    if (!is_mem && row >= B_ROWS) return;

    const float* src = is_mem ? (mem + (size_t)row * DIM) : (x + (size_t)row * DIM);
    const float4* s4 = reinterpret_cast<const float4*>(src);

    float4 v[8];
    float ss = 0.f;
    #pragma unroll
    for (int j = 0; j < 8; j++) {
        v[j] = s4[lane + 32 * j];
        ss += v[j].x * v[j].x + v[j].y * v[j].y + v[j].z * v[j].z + v[j].w * v[j].w;
    }
    #pragma unroll
    for (int o = 16; o; o >>= 1) ss += __shfl_xor_sync(0xffffffffu, ss, o);
    float iv = 1.0f / fmaxf(sqrtf(ss), 1e-12f);
    if (lane == 0) {
        if (is_mem) g_minv[row] = iv;
        else        g_xinv[row] = iv;
    }
    float sc = is_mem ? iv : 1.0f;   // fold inv-norm into memory only (x scale rank-invariant)
    __nv_bfloat16* dst = (is_mem ? g_memb : g_xb) + (size_t)row * DIM;
    uint2* d2 = reinterpret_cast<uint2*>(dst);
    #pragma unroll
    for (int j = 0; j < 8; j++) {
        __nv_bfloat162 p0 = __floats2bfloat162_rn(v[j].x * sc, v[j].y * sc);
        __nv_bfloat162 p1 = __floats2bfloat162_rn(v[j].z * sc, v[j].w * sc);
        uint2 w;
        w.x = *reinterpret_cast<uint32_t*>(&p0);
        w.y = *reinterpret_cast<uint32_t*>(&p1);
        d2[lane + 32 * j] = w;
    }
}

// ---------------- coarse GEMM (bf16 HMMA, proven) + per-tile top-8 ----------------
__global__ __launch_bounds__(256) void gemm_topk_kernel() {
    extern __shared__ char smem[];
    const int tid = threadIdx.x;
    const int bm = blockIdx.x;   // fast dim -> consecutive CTAs share B tile in L2
    const int bn = blockIdx.y;
    const uint32_t smem_u = (uint32_t)__cvta_generic_to_shared(smem);

    const int r0 = tid >> 2;
    const int ch = tid & 3;
    const __nv_bfloat16* gA0 = g_xb   + ((size_t)(bm * BM + r0)      * DIM + ch * 8);
    const __nv_bfloat16* gA1 = g_xb   + ((size_t)(bm * BM + r0 + 64) * DIM + ch * 8);
    const __nv_bfloat16* gB0 = g_memb + ((size_t)(bn * BN + r0)      * DIM + ch * 8);
    const __nv_bfloat16* gB1 = g_memb + ((size_t)(bn * BN + r0 + 64) * DIM + ch * 8);

    const uint32_t sa0 = (r0 * SROW + ch * 8) * 2;
    const uint32_t sa1 = ((r0 + 64) * SROW + ch * 8) * 2;

    float acc[4][4][4];
    #pragma unroll
    for (int i = 0; i < 4; i++)
        #pragma unroll
        for (int j = 0; j < 4; j++)
            #pragma unroll
            for (int q = 0; q < 4; q++) acc[i][j][q] = 0.f;

    const int lane = tid & 31;
    const int wm = ((tid >> 5) & 1) * 64;
    const int wn = (tid >> 6) * 32;

    {
        uint32_t base = smem_u;
        cp16(base + sa0, gA0);
        cp16(base + sa1, gA1);
        cp16(base + BM * SROW * 2 + sa0, gB0);
        cp16(base + BM * SROW * 2 + sa1, gB1);
        cp_commit();
    }

    const int NK = DIM / BK;  // 32
    for (int it = 0; it < NK; ++it) {
        if (it + 1 < NK) {
            uint32_t base = smem_u + ((it + 1) & 1) * STAGE_BYTES;
            size_t koff = (size_t)(it + 1) * BK;
            cp16(base + sa0, gA0 + koff);
            cp16(base + sa1, gA1 + koff);
            cp16(base + BM * SROW * 2 + sa0, gB0 + koff);
            cp16(base + BM * SROW * 2 + sa1, gB1 + koff);
            cp_commit();
            asm volatile("cp.async.wait_group 1;");
        } else {
            asm volatile("cp.async.wait_group 0;");
        }
        __syncthreads();

        uint32_t abase = smem_u + (it & 1) * STAGE_BYTES;
        uint32_t bbase = abase + BM * SROW * 2;
        #pragma unroll
        for (int kb = 0; kb < 2; ++kb) {
            uint32_t a[4][4];
            #pragma unroll
            for (int mi = 0; mi < 4; ++mi) {
                uint32_t ad = abase +
                    ((wm + mi * 16 + (lane & 15)) * SROW + kb * 16 + (lane >> 4) * 8) * 2;
                ldsm4(a[mi], ad);
            }
            uint32_t bfr[4][2];
            #pragma unroll
            for (int bp = 0; bp < 2; ++bp) {
                int mat = lane >> 3;
                uint32_t bd = bbase +
                    ((wn + bp * 16 + (mat >> 1) * 8 + (lane & 7)) * SROW +
                     kb * 16 + (mat & 1) * 8) * 2;
                uint32_t r[4];
                ldsm4(r, bd);
                bfr[bp * 2 + 0][0] = r[0]; bfr[bp * 2 + 0][1] = r[1];
                bfr[bp * 2 + 1][0] = r[2]; bfr[bp * 2 + 1][1] = r[3];
            }
            #pragma unroll
            for (int mi = 0; mi < 4; ++mi)
                #pragma unroll
                for (int ni = 0; ni < 4; ++ni)
                    mma16816(acc[mi][ni], a[mi], bfr[ni][0], bfr[ni][1]);
        }
        __syncthreads();
    }

    // epilogue: dump sims to smem, per-row top-8
    float* Cs = reinterpret_cast<float*>(smem);
    #pragma unroll
    for (int mi = 0; mi < 4; ++mi) {
        #pragma unroll
        for (int ni = 0; ni < 4; ++ni) {
            int rb = wm + mi * 16 + (lane >> 2);
            int cb = wn + ni * 8 + (lane & 3) * 2;
            Cs[rb * CS_STRIDE + cb]             = acc[mi][ni][0];
            Cs[rb * CS_STRIDE + cb + 1]         = acc[mi][ni][1];
            Cs[(rb + 8) * CS_STRIDE + cb]       = acc[mi][ni][2];
            Cs[(rb + 8) * CS_STRIDE + cb + 1]   = acc[mi][ni][3];
        }
    }
    __syncthreads();

    if (tid < BM) {
        const float* rowp = Cs + tid * CS_STRIDE;
        float tv[CAND_PER_TILE];
        int   tc[CAND_PER_TILE];
        #pragma unroll
        for (int i = 0; i < CAND_PER_TILE; i++) { tv[i] = -1e30f; tc[i] = 0; }
        for (int c = 0; c < BN; ++c) {
            float v = rowp[c];
            if (v > tv[CAND_PER_TILE - 1]) {
                int p = CAND_PER_TILE - 1;
                while (p > 0 && v > tv[p - 1]) { tv[p] = tv[p - 1]; tc[p] = tc[p - 1]; --p; }
                tv[p] = v; tc[p] = c;
            }
        }
        size_t base = ((size_t)(bm * BM + tid) * NTILES + bn) * CAND_PER_TILE;
        #pragma unroll
        for (int i = 0; i < CAND_PER_TILE; i++) {
            g_cv[base + i] = tv[i];
            g_ci[base + i] = bn * BN + tc[i];
        }
    }
}

// ---------------- phase 2: exact rescore, top-5, softmax, weighted gather ----------------
__global__ __launch_bounds__(256) void rescore_out_kernel(const float* __restrict__ x,
                                                          const float* __restrict__ mem,
                                                          float* __restrict__ out) {
    const int row = blockIdx.x;
    const int tid = threadIdx.x, lane = tid & 31, warp = tid >> 5;
    __shared__ float sv[CAND_PER_ROW];
    __shared__ float wv[8];
    __shared__ int   wp[8];
    __shared__ int   cpos[RESCORE];
    __shared__ float ev[RESCORE];
    __shared__ int   em[RESCORE];
    __shared__ float wgt[TOPK];
    __shared__ int   sidx[TOPK];

    const float4* cv4 = reinterpret_cast<const float4*>(g_cv + (size_t)row * CAND_PER_ROW);
    float4* sv4 = reinterpret_cast<float4*>(sv);
    for (int j = tid; j < CAND_PER_ROW / 4; j += 256) sv4[j] = cv4[j];
    __syncthreads();

    // approx top-16 by coarse score (iterative extract-max)
    for (int i = 0; i < RESCORE; ++i) {
        float best = -1e30f; int bp = -1;
        for (int j = tid; j < CAND_PER_ROW; j += 256) {
            float v = sv[j];
            if (v > best) { best = v; bp = j; }
        }
        #pragma unroll
        for (int o = 16; o; o >>= 1) {
            float ov = __shfl_down_sync(0xffffffffu, best, o);
            int   op = __shfl_down_sync(0xffffffffu, bp, o);
            if (ov > best) { best = ov; bp = op; }
        }
        if (lane == 0) { wv[warp] = best; wp[warp] = bp; }
        __syncthreads();
        if (tid == 0) {
            float bb = wv[0]; int pp = wp[0];
            #pragma unroll
            for (int w2 = 1; w2 < 8; w2++) if (wv[w2] > bb) { bb = wv[w2]; pp = wp[w2]; }
            cpos[i] = pp;
            sv[pp] = -1e30f;
        }
        __syncthreads();
    }

    // exact fp32 rescore of 16 candidates (2 per warp)
    const float4* xr = reinterpret_cast<const float4*>(x + (size_t)row * DIM);
    for (int i = warp; i < RESCORE; i += 8) {
        int mi = g_ci[(size_t)row * CAND_PER_ROW + cpos[i]];
        const float4* mr = reinterpret_cast<const float4*>(mem + (size_t)mi * DIM);
        float s = 0.f;
        for (int j = lane; j < DIM / 4; j += 32) {
            float4 a = xr[j], b = mr[j];
            s += a.x * b.x + a.y * b.y + a.z * b.z + a.w * b.w;
        }
        #pragma unroll
        for (int o = 16; o; o >>= 1) s += __shfl_down_sync(0xffffffffu, s, o);
        if (lane == 0) { ev[i] = s * g_minv[mi] * g_xinv[row]; em[i] = mi; }
    }
    __syncthreads();

    if (tid == 0) {
        bool used[RESCORE];
        #pragma unroll
        for (int i = 0; i < RESCORE; i++) used[i] = false;
        float tv[TOPK]; int ti[TOPK];
        #pragma unroll
        for (int r = 0; r < TOPK; ++r) {
            float bb = -1e30f; int pp = 0;
            for (int i = 0; i < RESCORE; i++)
                if (!used[i] && ev[i] > bb) { bb = ev[i]; pp = i; }
            used[pp] = true; tv[r] = bb; ti[r] = pp;
        }
        float mx = tv[0];
        float e[TOPK], se = 0.f;
        #pragma unroll
        for (int i = 0; i < TOPK; i++) { e[i] = expf(tv[i] - mx); se += e[i]; }
        #pragma unroll
        for (int i = 0; i < TOPK; i++) { wgt[i] = e[i] / se; sidx[i] = em[ti[i]]; }
    }
    __syncthreads();

    // weighted gather of raw memory rows
    float4 accv = make_float4(0.f, 0.f, 0.f, 0.f);
    #pragma unroll
    for (int i = 0; i < TOPK; i++) {
        const float4* mr = reinterpret_cast<const float4*>(mem + (size_t)sidx[i] * DIM);
        float4 m = mr[tid];
        float wg = wgt[i];
        accv.x += wg * m.x; accv.y += wg * m.y; accv.z += wg * m.z; accv.w += wg * m.w;
    }
    reinterpret_cast<float4*>(out + (size_t)row * DIM)[tid] = accv;
}

// ---------------- launch ----------------
extern "C" void kernel_launch(void* const* d_in, const int* in_sizes, int n_in,
                              void* d_out, int out_size) {
    const float* x   = (const float*)d_in[0];
    const float* mem = (const float*)d_in[1];
    float* out = (float*)d_out;

    cudaFuncSetAttribute(gemm_topk_kernel,
                         cudaFuncAttributeMaxDynamicSharedMemorySize, SMEM_BYTES);

    prep_all_kernel<<<(C_ROWS + B_ROWS) / 8, 256>>>(mem, x);
    gemm_topk_kernel<<<dim3(B_ROWS / BM, NTILES), 256, SMEM_BYTES>>>();
    rescore_out_kernel<<<B_ROWS, 256>>>(x, mem, out);
}

// round 13
// speedup vs baseline: 1.0164x; 1.0127x over previous
#include <cuda_runtime.h>
#include <cuda_bf16.h>
#include <cstdint>
#include <cstddef>

// ---------------- problem constants ----------------
#define B_ROWS 4096
#define C_ROWS 65536
#define DIM    1024
#define TOPK   5

// ---------------- GEMM tiling (proven R2/R10 config) ----------------
#define BM 128
#define BN 128
#define BK 32
#define NTILES (C_ROWS / BN)          // 512
#define CAND_PER_TILE 8
#define CAND_PER_ROW (NTILES * CAND_PER_TILE)  // 4096
#define RESCORE 8

#define SROW 40
#define STAGE_BYTES (2 * BM * SROW * 2)        // 20480
#define CS_STRIDE 129
#define SMEM_BYTES (BM * CS_STRIDE * 4)        // 66048

// ---------------- device scratch ----------------
__device__ __align__(16) __nv_bfloat16 g_memb[(size_t)C_ROWS * DIM]; // normalized bf16
__device__ __align__(16) __nv_bfloat16 g_xb[(size_t)B_ROWS * DIM];   // raw bf16
__device__ float g_minv[C_ROWS];
__device__ float g_xinv[B_ROWS];
__device__ __align__(16) float g_cv[(size_t)B_ROWS * CAND_PER_ROW];
__device__ __align__(16) int   g_ci[(size_t)B_ROWS * CAND_PER_ROW];

// ---------------- PTX helpers ----------------
__device__ __forceinline__ void cp16(uint32_t saddr, const void* gaddr) {
    asm volatile("cp.async.cg.shared.global [%0], [%1], 16;" :: "r"(saddr), "l"(gaddr));
}
__device__ __forceinline__ void cp_commit() {
    asm volatile("cp.async.commit_group;" ::: "memory");
}
__device__ __forceinline__ void ldsm4(uint32_t (&r)[4], uint32_t addr) {
    asm volatile("ldmatrix.sync.aligned.m8n8.x4.shared.b16 {%0,%1,%2,%3}, [%4];"
                 : "=r"(r[0]), "=r"(r[1]), "=r"(r[2]), "=r"(r[3]) : "r"(addr));
}
__device__ __forceinline__ void mma16816(float (&c)[4], const uint32_t (&a)[4],
                                         uint32_t b0, uint32_t b1) {
    asm volatile(
        "mma.sync.aligned.m16n8k16.row.col.f32.bf16.bf16.f32 "
        "{%0,%1,%2,%3},{%4,%5,%6,%7},{%8,%9},{%0,%1,%2,%3};"
        : "+f"(c[0]), "+f"(c[1]), "+f"(c[2]), "+f"(c[3])
        : "r"(a[0]), "r"(a[1]), "r"(a[2]), "r"(a[3]), "r"(b0), "r"(b1));
}

// ---------------- fused prep: warp-per-row (measured 56us, 84% HBM) ----------------
__global__ __launch_bounds__(256) void prep_all_kernel(const float* __restrict__ mem,
                                                       const float* __restrict__ x) {
    const int gw = blockIdx.x * 8 + (threadIdx.x >> 5);   // global warp id
    const int lane = threadIdx.x & 31;
    const bool is_mem = (gw < C_ROWS);
    const int row = is_mem ? gw : gw - C_ROWS;
    if (!is_mem && row >= B_ROWS) return;

    const float* src = is_mem ? (mem + (size_t)row * DIM) : (x + (size_t)row * DIM);
    const float4* s4 = reinterpret_cast<const float4*>(src);

    float4 v[8];
    float ss = 0.f;
    #pragma unroll
    for (int j = 0; j < 8; j++) {
        v[j] = s4[lane + 32 * j];
        ss += v[j].x * v[j].x + v[j].y * v[j].y + v[j].z * v[j].z + v[j].w * v[j].w;
    }
    #pragma unroll
    for (int o = 16; o; o >>= 1) ss += __shfl_xor_sync(0xffffffffu, ss, o);
    float iv = 1.0f / fmaxf(sqrtf(ss), 1e-12f);
    if (lane == 0) {
        if (is_mem) g_minv[row] = iv;
        else        g_xinv[row] = iv;
    }
    float sc = is_mem ? iv : 1.0f;   // fold inv-norm into memory only (x scale rank-invariant)
    __nv_bfloat16* dst = (is_mem ? g_memb : g_xb) + (size_t)row * DIM;
    uint2* d2 = reinterpret_cast<uint2*>(dst);
    #pragma unroll
    for (int j = 0; j < 8; j++) {
        __nv_bfloat162 p0 = __floats2bfloat162_rn(v[j].x * sc, v[j].y * sc);
        __nv_bfloat162 p1 = __floats2bfloat162_rn(v[j].z * sc, v[j].w * sc);
        uint2 w;
        w.x = *reinterpret_cast<uint32_t*>(&p0);
        w.y = *reinterpret_cast<uint32_t*>(&p1);
        d2[lane + 32 * j] = w;
    }
}

// ---------------- coarse GEMM (bf16 HMMA, proven) + per-tile top-8 ----------------
__global__ __launch_bounds__(256) void gemm_topk_kernel() {
    extern __shared__ char smem[];
    const int tid = threadIdx.x;
    const int bm = blockIdx.x;   // fast dim -> consecutive CTAs share B tile in L2
    const int bn = blockIdx.y;
    const uint32_t smem_u = (uint32_t)__cvta_generic_to_shared(smem);

    const int r0 = tid >> 2;
    const int ch = tid & 3;
    const __nv_bfloat16* gA0 = g_xb   + ((size_t)(bm * BM + r0)      * DIM + ch * 8);
    const __nv_bfloat16* gA1 = g_xb   + ((size_t)(bm * BM + r0 + 64) * DIM + ch * 8);
    const __nv_bfloat16* gB0 = g_memb + ((size_t)(bn * BN + r0)      * DIM + ch * 8);
    const __nv_bfloat16* gB1 = g_memb + ((size_t)(bn * BN + r0 + 64) * DIM + ch * 8);

    const uint32_t sa0 = (r0 * SROW + ch * 8) * 2;
    const uint32_t sa1 = ((r0 + 64) * SROW + ch * 8) * 2;

    float acc[4][4][4];
    #pragma unroll
    for (int i = 0; i < 4; i++)
        #pragma unroll
        for (int j = 0; j < 4; j++)
            #pragma unroll
            for (int q = 0; q < 4; q++) acc[i][j][q] = 0.f;

    const int lane = tid & 31;
    const int wm = ((tid >> 5) & 1) * 64;
    const int wn = (tid >> 6) * 32;

    {
        uint32_t base = smem_u;
        cp16(base + sa0, gA0);
        cp16(base + sa1, gA1);
        cp16(base + BM * SROW * 2 + sa0, gB0);
        cp16(base + BM * SROW * 2 + sa1, gB1);
        cp_commit();
    }

    const int NK = DIM / BK;  // 32
    for (int it = 0; it < NK; ++it) {
        if (it + 1 < NK) {
            uint32_t base = smem_u + ((it + 1) & 1) * STAGE_BYTES;
            size_t koff = (size_t)(it + 1) * BK;
            cp16(base + sa0, gA0 + koff);
            cp16(base + sa1, gA1 + koff);
            cp16(base + BM * SROW * 2 + sa0, gB0 + koff);
            cp16(base + BM * SROW * 2 + sa1, gB1 + koff);
            cp_commit();
            asm volatile("cp.async.wait_group 1;");
        } else {
            asm volatile("cp.async.wait_group 0;");
        }
        __syncthreads();

        uint32_t abase = smem_u + (it & 1) * STAGE_BYTES;
        uint32_t bbase = abase + BM * SROW * 2;
        #pragma unroll
        for (int kb = 0; kb < 2; ++kb) {
            uint32_t a[4][4];
            #pragma unroll
            for (int mi = 0; mi < 4; ++mi) {
                uint32_t ad = abase +
                    ((wm + mi * 16 + (lane & 15)) * SROW + kb * 16 + (lane >> 4) * 8) * 2;
                ldsm4(a[mi], ad);
            }
            uint32_t bfr[4][2];
            #pragma unroll
            for (int bp = 0; bp < 2; ++bp) {
                int mat = lane >> 3;
                uint32_t bd = bbase +
                    ((wn + bp * 16 + (mat >> 1) * 8 + (lane & 7)) * SROW +
                     kb * 16 + (mat & 1) * 8) * 2;
                uint32_t r[4];
                ldsm4(r, bd);
                bfr[bp * 2 + 0][0] = r[0]; bfr[bp * 2 + 0][1] = r[1];
                bfr[bp * 2 + 1][0] = r[2]; bfr[bp * 2 + 1][1] = r[3];
            }
            #pragma unroll
            for (int mi = 0; mi < 4; ++mi)
                #pragma unroll
                for (int ni = 0; ni < 4; ++ni)
                    mma16816(acc[mi][ni], a[mi], bfr[ni][0], bfr[ni][1]);
        }
        __syncthreads();
    }

    // epilogue: dump sims to smem, per-row top-8
    float* Cs = reinterpret_cast<float*>(smem);
    #pragma unroll
    for (int mi = 0; mi < 4; ++mi) {
        #pragma unroll
        for (int ni = 0; ni < 4; ++ni) {
            int rb = wm + mi * 16 + (lane >> 2);
            int cb = wn + ni * 8 + (lane & 3) * 2;
            Cs[rb * CS_STRIDE + cb]             = acc[mi][ni][0];
            Cs[rb * CS_STRIDE + cb + 1]         = acc[mi][ni][1];
            Cs[(rb + 8) * CS_STRIDE + cb]       = acc[mi][ni][2];
            Cs[(rb + 8) * CS_STRIDE + cb + 1]   = acc[mi][ni][3];
        }
    }
    __syncthreads();

    if (tid < BM) {
        const float* rowp = Cs + tid * CS_STRIDE;
        float tv[CAND_PER_TILE];
        int   tc[CAND_PER_TILE];
        #pragma unroll
        for (int i = 0; i < CAND_PER_TILE; i++) { tv[i] = -1e30f; tc[i] = 0; }
        for (int c = 0; c < BN; ++c) {
            float v = rowp[c];
            if (v > tv[CAND_PER_TILE - 1]) {
                int p = CAND_PER_TILE - 1;
                while (p > 0 && v > tv[p - 1]) { tv[p] = tv[p - 1]; tc[p] = tc[p - 1]; --p; }
                tv[p] = v; tc[p] = c;
            }
        }
        size_t base = ((size_t)(bm * BM + tid) * NTILES + bn) * CAND_PER_TILE;
        #pragma unroll
        for (int i = 0; i < CAND_PER_TILE; i++) {
            g_cv[base + i] = tv[i];
            g_ci[base + i] = bn * BN + tc[i];
        }
    }
}

// ---------------- phase 2: exact rescore (top-8), top-5, softmax, gather ----------------
__global__ __launch_bounds__(256) void rescore_out_kernel(const float* __restrict__ x,
                                                          const float* __restrict__ mem,
                                                          float* __restrict__ out) {
    const int row = blockIdx.x;
    const int tid = threadIdx.x, lane = tid & 31, warp = tid >> 5;
    __shared__ float sv[CAND_PER_ROW];
    __shared__ float wv[8];
    __shared__ int   wp[8];
    __shared__ int   cpos[RESCORE];
    __shared__ float ev[RESCORE];
    __shared__ int   em[RESCORE];
    __shared__ float wgt[TOPK];
    __shared__ int   sidx[TOPK];

    const float4* cv4 = reinterpret_cast<const float4*>(g_cv + (size_t)row * CAND_PER_ROW);
    float4* sv4 = reinterpret_cast<float4*>(sv);
    for (int j = tid; j < CAND_PER_ROW / 4; j += 256) sv4[j] = cv4[j];
    __syncthreads();

    // approx top-8 by coarse score (iterative extract-max; margin >> bf16 noise)
    for (int i = 0; i < RESCORE; ++i) {
        float best = -1e30f; int bp = -1;
        for (int j = tid; j < CAND_PER_ROW; j += 256) {
            float v = sv[j];
            if (v > best) { best = v; bp = j; }
        }
        #pragma unroll
        for (int o = 16; o; o >>= 1) {
            float ov = __shfl_down_sync(0xffffffffu, best, o);
            int   op = __shfl_down_sync(0xffffffffu, bp, o);
            if (ov > best) { best = ov; bp = op; }
        }
        if (lane == 0) { wv[warp] = best; wp[warp] = bp; }
        __syncthreads();
        if (tid == 0) {
            float bb = wv[0]; int pp = wp[0];
            #pragma unroll
            for (int w2 = 1; w2 < 8; w2++) if (wv[w2] > bb) { bb = wv[w2]; pp = wp[w2]; }
            cpos[i] = pp;
            sv[pp] = -1e30f;
        }
        __syncthreads();
    }

    // exact fp32 rescore of 8 candidates (1 per warp)
    const float4* xr = reinterpret_cast<const float4*>(x + (size_t)row * DIM);
    {
        int i = warp;
        int mi = g_ci[(size_t)row * CAND_PER_ROW + cpos[i]];
        const float4* mr = reinterpret_cast<const float4*>(mem + (size_t)mi * DIM);
        float s = 0.f;
        #pragma unroll
        for (int j = 0; j < 8; j++) {
            float4 a = xr[lane + 32 * j], b = mr[lane + 32 * j];
            s += a.x * b.x + a.y * b.y + a.z * b.z + a.w * b.w;
        }
        #pragma unroll
        for (int o = 16; o; o >>= 1) s += __shfl_down_sync(0xffffffffu, s, o);
        if (lane == 0) { ev[i] = s * g_minv[mi] * g_xinv[row]; em[i] = mi; }
    }
    __syncthreads();

    if (tid == 0) {
        bool used[RESCORE];
        #pragma unroll
        for (int i = 0; i < RESCORE; i++) used[i] = false;
        float tv[TOPK]; int ti[TOPK];
        #pragma unroll
        for (int r = 0; r < TOPK; ++r) {
            float bb = -1e30f; int pp = 0;
            for (int i = 0; i < RESCORE; i++)
                if (!used[i] && ev[i] > bb) { bb = ev[i]; pp = i; }
            used[pp] = true; tv[r] = bb; ti[r] = pp;
        }
        float mx = tv[0];
        float e[TOPK], se = 0.f;
        #pragma unroll
        for (int i = 0; i < TOPK; i++) { e[i] = expf(tv[i] - mx); se += e[i]; }
        #pragma unroll
        for (int i = 0; i < TOPK; i++) { wgt[i] = e[i] / se; sidx[i] = em[ti[i]]; }
    }
    __syncthreads();

    // weighted gather of raw memory rows
    float4 accv = make_float4(0.f, 0.f, 0.f, 0.f);
    #pragma unroll
    for (int i = 0; i < TOPK; i++) {
        const float4* mr = reinterpret_cast<const float4*>(mem + (size_t)sidx[i] * DIM);
        float4 m = mr[tid];
        float wg = wgt[i];
        accv.x += wg * m.x; accv.y += wg * m.y; accv.z += wg * m.z; accv.w += wg * m.w;
    }
    reinterpret_cast<float4*>(out + (size_t)row * DIM)[tid] = accv;
}

// ---------------- launch ----------------
extern "C" void kernel_launch(void* const* d_in, const int* in_sizes, int n_in,
                              void* d_out, int out_size) {
    const float* x   = (const float*)d_in[0];
    const float* mem = (const float*)d_in[1];
    float* out = (float*)d_out;

    cudaFuncSetAttribute(gemm_topk_kernel,
                         cudaFuncAttributeMaxDynamicSharedMemorySize, SMEM_BYTES);

    prep_all_kernel<<<(C_ROWS + B_ROWS) / 8, 256>>>(mem, x);
    gemm_topk_kernel<<<dim3(B_ROWS / BM, NTILES), 256, SMEM_BYTES>>>();
    rescore_out_kernel<<<B_ROWS, 256>>>(x, mem, out);
}

// round 14
// speedup vs baseline: 1.3451x; 1.3234x over previous
#include <cuda_runtime.h>
#include <cuda_bf16.h>
#include <cstdint>
#include <cstddef>

// ---------------- problem constants ----------------
#define B_ROWS 4096
#define C_ROWS 65536
#define DIM    1024
#define TOPK   5

// ---------------- GEMM tiling (proven R2/R10 config) ----------------
#define BM 128
#define BN 128
#define BK 32
#define NTILES (C_ROWS / BN)          // 512
#define CAND_PER_TILE 4
#define CAND_PER_ROW (NTILES * CAND_PER_TILE)  // 2048
#define RESCORE 8

#define SROW 40
#define STAGE_BYTES (2 * BM * SROW * 2)        // 20480
#define CS_STRIDE 129
#define SMEM_BYTES (BM * CS_STRIDE * 4)        // 66048

// ---------------- device scratch ----------------
__device__ __align__(16) __nv_bfloat16 g_memb[(size_t)C_ROWS * DIM]; // normalized bf16
__device__ __align__(16) __nv_bfloat16 g_xb[(size_t)B_ROWS * DIM];   // raw bf16
__device__ float g_minv[C_ROWS];
__device__ float g_xinv[B_ROWS];
__device__ __align__(16) float g_cv[(size_t)B_ROWS * CAND_PER_ROW];
__device__ __align__(16) int   g_ci[(size_t)B_ROWS * CAND_PER_ROW];

// ---------------- PTX helpers ----------------
__device__ __forceinline__ void cp16(uint32_t saddr, const void* gaddr) {
    asm volatile("cp.async.cg.shared.global [%0], [%1], 16;" :: "r"(saddr), "l"(gaddr));
}
__device__ __forceinline__ void cp_commit() {
    asm volatile("cp.async.commit_group;" ::: "memory");
}
__device__ __forceinline__ void ldsm4(uint32_t (&r)[4], uint32_t addr) {
    asm volatile("ldmatrix.sync.aligned.m8n8.x4.shared.b16 {%0,%1,%2,%3}, [%4];"
                 : "=r"(r[0]), "=r"(r[1]), "=r"(r[2]), "=r"(r[3]) : "r"(addr));
}
__device__ __forceinline__ void mma16816(float (&c)[4], const uint32_t (&a)[4],
                                         uint32_t b0, uint32_t b1) {
    asm volatile(
        "mma.sync.aligned.m16n8k16.row.col.f32.bf16.bf16.f32 "
        "{%0,%1,%2,%3},{%4,%5,%6,%7},{%8,%9},{%0,%1,%2,%3};"
        : "+f"(c[0]), "+f"(c[1]), "+f"(c[2]), "+f"(c[3])
        : "r"(a[0]), "r"(a[1]), "r"(a[2]), "r"(a[3]), "r"(b0), "r"(b1));
}

// ---------------- fused prep: warp-per-row (measured ~57us, 82-84% HBM) ----------------
__global__ __launch_bounds__(256) void prep_all_kernel(const float* __restrict__ mem,
                                                       const float* __restrict__ x) {
    const int gw = blockIdx.x * 8 + (threadIdx.x >> 5);   // global warp id
    const int lane = threadIdx.x & 31;
    const bool is_mem = (gw < C_ROWS);
    const int row = is_mem ? gw : gw - C_ROWS;
    if (!is_mem && row >= B_ROWS) return;

    const float* src = is_mem ? (mem + (size_t)row * DIM) : (x + (size_t)row * DIM);
    const float4* s4 = reinterpret_cast<const float4*>(src);

    float4 v[8];
    float ss = 0.f;
    #pragma unroll
    for (int j = 0; j < 8; j++) {
        v[j] = s4[lane + 32 * j];
        ss += v[j].x * v[j].x + v[j].y * v[j].y + v[j].z * v[j].z + v[j].w * v[j].w;
    }
    #pragma unroll
    for (int o = 16; o; o >>= 1) ss += __shfl_xor_sync(0xffffffffu, ss, o);
    float iv = 1.0f / fmaxf(sqrtf(ss), 1e-12f);
    if (lane == 0) {
        if (is_mem) g_minv[row] = iv;
        else        g_xinv[row] = iv;
    }
    float sc = is_mem ? iv : 1.0f;   // fold inv-norm into memory only (x scale rank-invariant)
    __nv_bfloat16* dst = (is_mem ? g_memb : g_xb) + (size_t)row * DIM;
    uint2* d2 = reinterpret_cast<uint2*>(dst);
    #pragma unroll
    for (int j = 0; j < 8; j++) {
        __nv_bfloat162 p0 = __floats2bfloat162_rn(v[j].x * sc, v[j].y * sc);
        __nv_bfloat162 p1 = __floats2bfloat162_rn(v[j].z * sc, v[j].w * sc);
        uint2 w;
        w.x = *reinterpret_cast<uint32_t*>(&p0);
        w.y = *reinterpret_cast<uint32_t*>(&p1);
        d2[lane + 32 * j] = w;
    }
}

// ---------------- coarse GEMM (bf16 HMMA, proven) + per-tile top-4 ----------------
__global__ __launch_bounds__(256) void gemm_topk_kernel() {
    extern __shared__ char smem[];
    const int tid = threadIdx.x;
    const int bm = blockIdx.x;   // fast dim -> consecutive CTAs share B tile in L2
    const int bn = blockIdx.y;
    const uint32_t smem_u = (uint32_t)__cvta_generic_to_shared(smem);

    const int r0 = tid >> 2;
    const int ch = tid & 3;
    const __nv_bfloat16* gA0 = g_xb   + ((size_t)(bm * BM + r0)      * DIM + ch * 8);
    const __nv_bfloat16* gA1 = g_xb   + ((size_t)(bm * BM + r0 + 64) * DIM + ch * 8);
    const __nv_bfloat16* gB0 = g_memb + ((size_t)(bn * BN + r0)      * DIM + ch * 8);
    const __nv_bfloat16* gB1 = g_memb + ((size_t)(bn * BN + r0 + 64) * DIM + ch * 8);

    const uint32_t sa0 = (r0 * SROW + ch * 8) * 2;
    const uint32_t sa1 = ((r0 + 64) * SROW + ch * 8) * 2;

    float acc[4][4][4];
    #pragma unroll
    for (int i = 0; i < 4; i++)
        #pragma unroll
        for (int j = 0; j < 4; j++)
            #pragma unroll
            for (int q = 0; q < 4; q++) acc[i][j][q] = 0.f;

    const int lane = tid & 31;
    const int wm = ((tid >> 5) & 1) * 64;
    const int wn = (tid >> 6) * 32;

    {
        uint32_t base = smem_u;
        cp16(base + sa0, gA0);
        cp16(base + sa1, gA1);
        cp16(base + BM * SROW * 2 + sa0, gB0);
        cp16(base + BM * SROW * 2 + sa1, gB1);
        cp_commit();
    }

    const int NK = DIM / BK;  // 32
    for (int it = 0; it < NK; ++it) {
        if (it + 1 < NK) {
            uint32_t base = smem_u + ((it + 1) & 1) * STAGE_BYTES;
            size_t koff = (size_t)(it + 1) * BK;
            cp16(base + sa0, gA0 + koff);
            cp16(base + sa1, gA1 + koff);
            cp16(base + BM * SROW * 2 + sa0, gB0 + koff);
            cp16(base + BM * SROW * 2 + sa1, gB1 + koff);
            cp_commit();
            asm volatile("cp.async.wait_group 1;");
        } else {
            asm volatile("cp.async.wait_group 0;");
        }
        __syncthreads();

        uint32_t abase = smem_u + (it & 1) * STAGE_BYTES;
        uint32_t bbase = abase + BM * SROW * 2;
        #pragma unroll
        for (int kb = 0; kb < 2; ++kb) {
            uint32_t a[4][4];
            #pragma unroll
            for (int mi = 0; mi < 4; ++mi) {
                uint32_t ad = abase +
                    ((wm + mi * 16 + (lane & 15)) * SROW + kb * 16 + (lane >> 4) * 8) * 2;
                ldsm4(a[mi], ad);
            }
            uint32_t bfr[4][2];
            #pragma unroll
            for (int bp = 0; bp < 2; ++bp) {
                int mat = lane >> 3;
                uint32_t bd = bbase +
                    ((wn + bp * 16 + (mat >> 1) * 8 + (lane & 7)) * SROW +
                     kb * 16 + (mat & 1) * 8) * 2;
                uint32_t r[4];
                ldsm4(r, bd);
                bfr[bp * 2 + 0][0] = r[0]; bfr[bp * 2 + 0][1] = r[1];
                bfr[bp * 2 + 1][0] = r[2]; bfr[bp * 2 + 1][1] = r[3];
            }
            #pragma unroll
            for (int mi = 0; mi < 4; ++mi)
                #pragma unroll
                for (int ni = 0; ni < 4; ++ni)
                    mma16816(acc[mi][ni], a[mi], bfr[ni][0], bfr[ni][1]);
        }
        __syncthreads();
    }

    // epilogue: dump sims to smem, per-row top-4
    float* Cs = reinterpret_cast<float*>(smem);
    #pragma unroll
    for (int mi = 0; mi < 4; ++mi) {
        #pragma unroll
        for (int ni = 0; ni < 4; ++ni) {
            int rb = wm + mi * 16 + (lane >> 2);
            int cb = wn + ni * 8 + (lane & 3) * 2;
            Cs[rb * CS_STRIDE + cb]             = acc[mi][ni][0];
            Cs[rb * CS_STRIDE + cb + 1]         = acc[mi][ni][1];
            Cs[(rb + 8) * CS_STRIDE + cb]       = acc[mi][ni][2];
            Cs[(rb + 8) * CS_STRIDE + cb + 1]   = acc[mi][ni][3];
        }
    }
    __syncthreads();

    if (tid < BM) {
        const float* rowp = Cs + tid * CS_STRIDE;
        float tv[CAND_PER_TILE];
        int   tc[CAND_PER_TILE];
        #pragma unroll
        for (int i = 0; i < CAND_PER_TILE; i++) { tv[i] = -1e30f; tc[i] = 0; }
        for (int c = 0; c < BN; ++c) {
            float v = rowp[c];
            if (v > tv[CAND_PER_TILE - 1]) {
                int p = CAND_PER_TILE - 1;
                while (p > 0 && v > tv[p - 1]) { tv[p] = tv[p - 1]; tc[p] = tc[p - 1]; --p; }
                tv[p] = v; tc[p] = c;
            }
        }
        size_t base = ((size_t)(bm * BM + tid) * NTILES + bn) * CAND_PER_TILE;
        #pragma unroll
        for (int i = 0; i < CAND_PER_TILE; i++) {
            g_cv[base + i] = tv[i];
            g_ci[base + i] = bn * BN + tc[i];
        }
    }
}

// ---------------- phase 2: exact rescore (top-8), top-5, softmax, gather ----------------
__global__ __launch_bounds__(256) void rescore_out_kernel(const float* __restrict__ x,
                                                          const float* __restrict__ mem,
                                                          float* __restrict__ out) {
    const int row = blockIdx.x;
    const int tid = threadIdx.x, lane = tid & 31, warp = tid >> 5;
    __shared__ float sv[CAND_PER_ROW];
    __shared__ float wv[8];
    __shared__ int   wp[8];
    __shared__ int   cpos[RESCORE];
    __shared__ float ev[RESCORE];
    __shared__ int   em[RESCORE];
    __shared__ float wgt[TOPK];
    __shared__ int   sidx[TOPK];

    const float4* cv4 = reinterpret_cast<const float4*>(g_cv + (size_t)row * CAND_PER_ROW);
    float4* sv4 = reinterpret_cast<float4*>(sv);
    for (int j = tid; j < CAND_PER_ROW / 4; j += 256) sv4[j] = cv4[j];
    __syncthreads();

    // approx top-8 by coarse score (iterative extract-max; margin >> bf16 noise)
    for (int i = 0; i < RESCORE; ++i) {
        float best = -1e30f; int bp = -1;
        for (int j = tid; j < CAND_PER_ROW; j += 256) {
            float v = sv[j];
            if (v > best) { best = v; bp = j; }
        }
        #pragma unroll
        for (int o = 16; o; o >>= 1) {
            float ov = __shfl_down_sync(0xffffffffu, best, o);
            int   op = __shfl_down_sync(0xffffffffu, bp, o);
            if (ov > best) { best = ov; bp = op; }
        }
        if (lane == 0) { wv[warp] = best; wp[warp] = bp; }
        __syncthreads();
        if (tid == 0) {
            float bb = wv[0]; int pp = wp[0];
            #pragma unroll
            for (int w2 = 1; w2 < 8; w2++) if (wv[w2] > bb) { bb = wv[w2]; pp = wp[w2]; }
            cpos[i] = pp;
            sv[pp] = -1e30f;
        }
        __syncthreads();
    }

    // exact fp32 rescore of 8 candidates (1 per warp)
    const float4* xr = reinterpret_cast<const float4*>(x + (size_t)row * DIM);
    {
        int i = warp;
        int mi = g_ci[(size_t)row * CAND_PER_ROW + cpos[i]];
        const float4* mr = reinterpret_cast<const float4*>(mem + (size_t)mi * DIM);
        float s = 0.f;
        #pragma unroll
        for (int j = 0; j < 8; j++) {
            float4 a = xr[lane + 32 * j], b = mr[lane + 32 * j];
            s += a.x * b.x + a.y * b.y + a.z * b.z + a.w * b.w;
        }
        #pragma unroll
        for (int o = 16; o; o >>= 1) s += __shfl_down_sync(0xffffffffu, s, o);
        if (lane == 0) { ev[i] = s * g_minv[mi] * g_xinv[row]; em[i] = mi; }
    }
    __syncthreads();

    if (tid == 0) {
        bool used[RESCORE];
        #pragma unroll
        for (int i = 0; i < RESCORE; i++) used[i] = false;
        float tv[TOPK]; int ti[TOPK];
        #pragma unroll
        for (int r = 0; r < TOPK; ++r) {
            float bb = -1e30f; int pp = 0;
            for (int i = 0; i < RESCORE; i++)
                if (!used[i] && ev[i] > bb) { bb = ev[i]; pp = i; }
            used[pp] = true; tv[r] = bb; ti[r] = pp;
        }
        float mx = tv[0];
        float e[TOPK], se = 0.f;
        #pragma unroll
        for (int i = 0; i < TOPK; i++) { e[i] = expf(tv[i] - mx); se += e[i]; }
        #pragma unroll
        for (int i = 0; i < TOPK; i++) { wgt[i] = e[i] / se; sidx[i] = em[ti[i]]; }
    }
    __syncthreads();

    // weighted gather of raw memory rows
    float4 accv = make_float4(0.f, 0.f, 0.f, 0.f);
    #pragma unroll
    for (int i = 0; i < TOPK; i++) {
        const float4* mr = reinterpret_cast<const float4*>(mem + (size_t)sidx[i] * DIM);
        float4 m = mr[tid];
        float wg = wgt[i];
        accv.x += wg * m.x; accv.y += wg * m.y; accv.z += wg * m.z; accv.w += wg * m.w;
    }
    reinterpret_cast<float4*>(out + (size_t)row * DIM)[tid] = accv;
}

// ---------------- launch ----------------
extern "C" void kernel_launch(void* const* d_in, const int* in_sizes, int n_in,
                              void* d_out, int out_size) {
    const float* x   = (const float*)d_in[0];
    const float* mem = (const float*)d_in[1];
    float* out = (float*)d_out;

    cudaFuncSetAttribute(gemm_topk_kernel,
                         cudaFuncAttributeMaxDynamicSharedMemorySize, SMEM_BYTES);

    prep_all_kernel<<<(C_ROWS + B_ROWS) / 8, 256>>>(mem, x);
    gemm_topk_kernel<<<dim3(B_ROWS / BM, NTILES), 256, SMEM_BYTES>>>();
    rescore_out_kernel<<<B_ROWS, 256>>>(x, mem, out);
}

// round 15
// speedup vs baseline: 1.8549x; 1.3790x over previous
#include <cuda_runtime.h>
#include <cuda_bf16.h>
#include <cstdint>
#include <cstddef>

// ---------------- problem constants ----------------
#define B_ROWS 4096
#define C_ROWS 65536
#define DIM    1024
#define TOPK   5

// ---------------- GEMM tiling (proven config) ----------------
#define BM 128
#define BN 128
#define BK 32
#define NTILES (C_ROWS / BN)          // 512
#define CAND_PER_TILE 4
#define CAND_PER_ROW (NTILES * CAND_PER_TILE)  // 2048
#define RESCORE 8

#define SROW 40
#define STAGE_BYTES (2 * BM * SROW * 2)        // 20480
#define CS_STRIDE 129
#define SMEM_BYTES (BM * CS_STRIDE * 4)        // 66048

// ---------------- device scratch ----------------
__device__ __align__(16) __nv_bfloat16 g_memb[(size_t)C_ROWS * DIM]; // normalized bf16
__device__ __align__(16) __nv_bfloat16 g_xb[(size_t)B_ROWS * DIM];   // raw bf16
__device__ float g_minv[C_ROWS];
__device__ float g_xinv[B_ROWS];
__device__ __align__(16) float g_cv[(size_t)B_ROWS * CAND_PER_ROW];
__device__ __align__(16) int   g_ci[(size_t)B_ROWS * CAND_PER_ROW];

// ---------------- PTX helpers ----------------
__device__ __forceinline__ void cp16(uint32_t saddr, const void* gaddr) {
    asm volatile("cp.async.cg.shared.global [%0], [%1], 16;" :: "r"(saddr), "l"(gaddr));
}
__device__ __forceinline__ void cp_commit() {
    asm volatile("cp.async.commit_group;" ::: "memory");
}
__device__ __forceinline__ void ldsm4(uint32_t (&r)[4], uint32_t addr) {
    asm volatile("ldmatrix.sync.aligned.m8n8.x4.shared.b16 {%0,%1,%2,%3}, [%4];"
                 : "=r"(r[0]), "=r"(r[1]), "=r"(r[2]), "=r"(r[3]) : "r"(addr));
}
__device__ __forceinline__ void mma16816(float (&c)[4], const uint32_t (&a)[4],
                                         uint32_t b0, uint32_t b1) {
    asm volatile(
        "mma.sync.aligned.m16n8k16.row.col.f32.bf16.bf16.f32 "
        "{%0,%1,%2,%3},{%4,%5,%6,%7},{%8,%9},{%0,%1,%2,%3};"
        : "+f"(c[0]), "+f"(c[1]), "+f"(c[2]), "+f"(c[3])
        : "r"(a[0]), "r"(a[1]), "r"(a[2]), "r"(a[3]), "r"(b0), "r"(b1));
}

// ---------------- fused prep: warp-per-row (measured ~57us, 82-84% HBM) ----------------
__global__ __launch_bounds__(256) void prep_all_kernel(const float* __restrict__ mem,
                                                       const float* __restrict__ x) {
    const int gw = blockIdx.x * 8 + (threadIdx.x >> 5);   // global warp id
    const int lane = threadIdx.x & 31;
    const bool is_mem = (gw < C_ROWS);
    const int row = is_mem ? gw : gw - C_ROWS;
    if (!is_mem && row >= B_ROWS) return;

    const float* src = is_mem ? (mem + (size_t)row * DIM) : (x + (size_t)row * DIM);
    const float4* s4 = reinterpret_cast<const float4*>(src);

    float4 v[8];
    float ss = 0.f;
    #pragma unroll
    for (int j = 0; j < 8; j++) {
        v[j] = s4[lane + 32 * j];
        ss += v[j].x * v[j].x + v[j].y * v[j].y + v[j].z * v[j].z + v[j].w * v[j].w;
    }
    #pragma unroll
    for (int o = 16; o; o >>= 1) ss += __shfl_xor_sync(0xffffffffu, ss, o);
    float iv = 1.0f / fmaxf(sqrtf(ss), 1e-12f);
    if (lane == 0) {
        if (is_mem) g_minv[row] = iv;
        else        g_xinv[row] = iv;
    }
    float sc = is_mem ? iv : 1.0f;   // fold inv-norm into memory only (x scale rank-invariant)
    __nv_bfloat16* dst = (is_mem ? g_memb : g_xb) + (size_t)row * DIM;
    uint2* d2 = reinterpret_cast<uint2*>(dst);
    #pragma unroll
    for (int j = 0; j < 8; j++) {
        __nv_bfloat162 p0 = __floats2bfloat162_rn(v[j].x * sc, v[j].y * sc);
        __nv_bfloat162 p1 = __floats2bfloat162_rn(v[j].z * sc, v[j].w * sc);
        uint2 w;
        w.x = *reinterpret_cast<uint32_t*>(&p0);
        w.y = *reinterpret_cast<uint32_t*>(&p1);
        d2[lane + 32 * j] = w;
    }
}

// ---------------- coarse GEMM (bf16 HMMA) + register-only per-row top-4 ----------------
__global__ __launch_bounds__(256) void gemm_topk_kernel() {
    extern __shared__ char smem[];
    const int tid = threadIdx.x;
    const int bm = blockIdx.x;   // fast dim -> consecutive CTAs share B tile in L2
    const int bn = blockIdx.y;
    const uint32_t smem_u = (uint32_t)__cvta_generic_to_shared(smem);

    const int r0 = tid >> 2;
    const int ch = tid & 3;
    const __nv_bfloat16* gA0 = g_xb   + ((size_t)(bm * BM + r0)      * DIM + ch * 8);
    const __nv_bfloat16* gA1 = g_xb   + ((size_t)(bm * BM + r0 + 64) * DIM + ch * 8);
    const __nv_bfloat16* gB0 = g_memb + ((size_t)(bn * BN + r0)      * DIM + ch * 8);
    const __nv_bfloat16* gB1 = g_memb + ((size_t)(bn * BN + r0 + 64) * DIM + ch * 8);

    const uint32_t sa0 = (r0 * SROW + ch * 8) * 2;
    const uint32_t sa1 = ((r0 + 64) * SROW + ch * 8) * 2;

    float acc[4][4][4];
    #pragma unroll
    for (int i = 0; i < 4; i++)
        #pragma unroll
        for (int j = 0; j < 4; j++)
            #pragma unroll
            for (int q = 0; q < 4; q++) acc[i][j][q] = 0.f;

    const int lane = tid & 31;
    const int wm = ((tid >> 5) & 1) * 64;
    const int wn = (tid >> 6) * 32;

    {
        uint32_t base = smem_u;
        cp16(base + sa0, gA0);
        cp16(base + sa1, gA1);
        cp16(base + BM * SROW * 2 + sa0, gB0);
        cp16(base + BM * SROW * 2 + sa1, gB1);
        cp_commit();
    }

    const int NK = DIM / BK;  // 32
    for (int it = 0; it < NK; ++it) {
        if (it + 1 < NK) {
            uint32_t base = smem_u + ((it + 1) & 1) * STAGE_BYTES;
            size_t koff = (size_t)(it + 1) * BK;
            cp16(base + sa0, gA0 + koff);
            cp16(base + sa1, gA1 + koff);
            cp16(base + BM * SROW * 2 + sa0, gB0 + koff);
            cp16(base + BM * SROW * 2 + sa1, gB1 + koff);
            cp_commit();
            asm volatile("cp.async.wait_group 1;");
        } else {
            asm volatile("cp.async.wait_group 0;");
        }
        __syncthreads();

        uint32_t abase = smem_u + (it & 1) * STAGE_BYTES;
        uint32_t bbase = abase + BM * SROW * 2;
        #pragma unroll
        for (int kb = 0; kb < 2; ++kb) {
            uint32_t a[4][4];
            #pragma unroll
            for (int mi = 0; mi < 4; ++mi) {
                uint32_t ad = abase +
                    ((wm + mi * 16 + (lane & 15)) * SROW + kb * 16 + (lane >> 4) * 8) * 2;
                ldsm4(a[mi], ad);
            }
            uint32_t bfr[4][2];
            #pragma unroll
            for (int bp = 0; bp < 2; ++bp) {
                int mat = lane >> 3;
                uint32_t bd = bbase +
                    ((wn + bp * 16 + (mat >> 1) * 8 + (lane & 7)) * SROW +
                     kb * 16 + (mat & 1) * 8) * 2;
                uint32_t r[4];
                ldsm4(r, bd);
                bfr[bp * 2 + 0][0] = r[0]; bfr[bp * 2 + 0][1] = r[1];
                bfr[bp * 2 + 1][0] = r[2]; bfr[bp * 2 + 1][1] = r[3];
            }
            #pragma unroll
            for (int mi = 0; mi < 4; ++mi)
                #pragma unroll
                for (int ni = 0; ni < 4; ++ni)
                    mma16816(acc[mi][ni], a[mi], bfr[ni][0], bfr[ni][1]);
        }
        __syncthreads();
    }

    // epilogue: dump sims to smem
    float* Cs = reinterpret_cast<float*>(smem);
    #pragma unroll
    for (int mi = 0; mi < 4; ++mi) {
        #pragma unroll
        for (int ni = 0; ni < 4; ++ni) {
            int rb = wm + mi * 16 + (lane >> 2);
            int cb = wn + ni * 8 + (lane & 3) * 2;
            Cs[rb * CS_STRIDE + cb]             = acc[mi][ni][0];
            Cs[rb * CS_STRIDE + cb + 1]         = acc[mi][ni][1];
            Cs[(rb + 8) * CS_STRIDE + cb]       = acc[mi][ni][2];
            Cs[(rb + 8) * CS_STRIDE + cb + 1]   = acc[mi][ni][3];
        }
    }
    __syncthreads();

    // per-row top-4 in NAMED scalar registers (no dynamic indexing -> no local mem)
    if (tid < BM) {
        const float* rowp = Cs + tid * CS_STRIDE;
        float v0 = -1e30f, v1 = -1e30f, v2 = -1e30f, v3 = -1e30f;
        int   c0 = 0, c1 = 0, c2 = 0, c3 = 0;
        #pragma unroll 4
        for (int c = 0; c < BN; ++c) {
            float v = rowp[c];
            if (v > v3) {
                if (v > v0) {
                    v3 = v2; c3 = c2; v2 = v1; c2 = c1; v1 = v0; c1 = c0; v0 = v; c0 = c;
                } else if (v > v1) {
                    v3 = v2; c3 = c2; v2 = v1; c2 = c1; v1 = v; c1 = c;
                } else if (v > v2) {
                    v3 = v2; c3 = c2; v2 = v; c2 = c;
                } else {
                    v3 = v; c3 = c;
                }
            }
        }
        size_t base = ((size_t)(bm * BM + tid) * NTILES + bn) * CAND_PER_TILE;
        g_cv[base + 0] = v0; g_ci[base + 0] = bn * BN + c0;
        g_cv[base + 1] = v1; g_ci[base + 1] = bn * BN + c1;
        g_cv[base + 2] = v2; g_ci[base + 2] = bn * BN + c2;
        g_cv[base + 3] = v3; g_ci[base + 3] = bn * BN + c3;
    }
}

// ---------------- phase 2: exact rescore (top-8), top-5, softmax, gather ----------------
__global__ __launch_bounds__(256) void rescore_out_kernel(const float* __restrict__ x,
                                                          const float* __restrict__ mem,
                                                          float* __restrict__ out) {
    const int row = blockIdx.x;
    const int tid = threadIdx.x, lane = tid & 31, warp = tid >> 5;
    __shared__ float sv[CAND_PER_ROW];
    __shared__ float wv[8];
    __shared__ int   wp[8];
    __shared__ int   cpos[RESCORE];
    __shared__ float ev[RESCORE];
    __shared__ int   em[RESCORE];
    __shared__ float wgt[TOPK];
    __shared__ int   sidx[TOPK];

    const float4* cv4 = reinterpret_cast<const float4*>(g_cv + (size_t)row * CAND_PER_ROW);
    float4* sv4 = reinterpret_cast<float4*>(sv);
    for (int j = tid; j < CAND_PER_ROW / 4; j += 256) sv4[j] = cv4[j];
    __syncthreads();

    // approx top-8 by coarse score (iterative extract-max; margin >> bf16 noise)
    for (int i = 0; i < RESCORE; ++i) {
        float best = -1e30f; int bp = -1;
        for (int j = tid; j < CAND_PER_ROW; j += 256) {
            float v = sv[j];
            if (v > best) { best = v; bp = j; }
        }
        #pragma unroll
        for (int o = 16; o; o >>= 1) {
            float ov = __shfl_down_sync(0xffffffffu, best, o);
            int   op = __shfl_down_sync(0xffffffffu, bp, o);
            if (ov > best) { best = ov; bp = op; }
        }
        if (lane == 0) { wv[warp] = best; wp[warp] = bp; }
        __syncthreads();
        if (tid == 0) {
            float bb = wv[0]; int pp = wp[0];
            #pragma unroll
            for (int w2 = 1; w2 < 8; w2++) if (wv[w2] > bb) { bb = wv[w2]; pp = wp[w2]; }
            cpos[i] = pp;
            sv[pp] = -1e30f;
        }
        __syncthreads();
    }

    // exact fp32 rescore of 8 candidates (1 per warp)
    const float4* xr = reinterpret_cast<const float4*>(x + (size_t)row * DIM);
    {
        int i = warp;
        int mi = g_ci[(size_t)row * CAND_PER_ROW + cpos[i]];
        const float4* mr = reinterpret_cast<const float4*>(mem + (size_t)mi * DIM);
        float s = 0.f;
        #pragma unroll
        for (int j = 0; j < 8; j++) {
            float4 a = xr[lane + 32 * j], b = mr[lane + 32 * j];
            s += a.x * b.x + a.y * b.y + a.z * b.z + a.w * b.w;
        }
        #pragma unroll
        for (int o = 16; o; o >>= 1) s += __shfl_down_sync(0xffffffffu, s, o);
        if (lane == 0) { ev[i] = s * g_minv[mi] * g_xinv[row]; em[i] = mi; }
    }
    __syncthreads();

    if (tid == 0) {
        bool used[RESCORE];
        #pragma unroll
        for (int i = 0; i < RESCORE; i++) used[i] = false;
        float tv[TOPK]; int ti[TOPK];
        #pragma unroll
        for (int r = 0; r < TOPK; ++r) {
            float bb = -1e30f; int pp = 0;
            for (int i = 0; i < RESCORE; i++)
                if (!used[i] && ev[i] > bb) { bb = ev[i]; pp = i; }
            used[pp] = true; tv[r] = bb; ti[r] = pp;
        }
        float mx = tv[0];
        float e[TOPK], se = 0.f;
        #pragma unroll
        for (int i = 0; i < TOPK; i++) { e[i] = expf(tv[i] - mx); se += e[i]; }
        #pragma unroll
        for (int i = 0; i < TOPK; i++) { wgt[i] = e[i] / se; sidx[i] = em[ti[i]]; }
    }
    __syncthreads();

    // weighted gather of raw memory rows
    float4 accv = make_float4(0.f, 0.f, 0.f, 0.f);
    #pragma unroll
    for (int i = 0; i < TOPK; i++) {
        const float4* mr = reinterpret_cast<const float4*>(mem + (size_t)sidx[i] * DIM);
        float4 m = mr[tid];
        float wg = wgt[i];
        accv.x += wg * m.x; accv.y += wg * m.y; accv.z += wg * m.z; accv.w += wg * m.w;
    }
    reinterpret_cast<float4*>(out + (size_t)row * DIM)[tid] = accv;
}

// ---------------- launch ----------------
extern "C" void kernel_launch(void* const* d_in, const int* in_sizes, int n_in,
                              void* d_out, int out_size) {
    const float* x   = (const float*)d_in[0];
    const float* mem = (const float*)d_in[1];
    float* out = (float*)d_out;

    cudaFuncSetAttribute(gemm_topk_kernel,
                         cudaFuncAttributeMaxDynamicSharedMemorySize, SMEM_BYTES);

    prep_all_kernel<<<(C_ROWS + B_ROWS) / 8, 256>>>(mem, x);
    gemm_topk_kernel<<<dim3(B_ROWS / BM, NTILES), 256, SMEM_BYTES>>>();
    rescore_out_kernel<<<B_ROWS, 256>>>(x, mem, out);
}

// round 16
// speedup vs baseline: 1.8938x; 1.0210x over previous
#include <cuda_runtime.h>
#include <cuda_bf16.h>
#include <cstdint>
#include <cstddef>

// ---------------- problem constants ----------------
#define B_ROWS 4096
#define C_ROWS 65536
#define DIM    1024
#define TOPK   5

// ---------------- GEMM tiling (proven config) ----------------
#define BM 128
#define BN 128
#define BK 32
#define NTILES (C_ROWS / BN)          // 512
#define CAND_PER_TILE 4
#define CAND_PER_ROW (NTILES * CAND_PER_TILE)  // 2048
#define RESCORE 8

#define SROW 40
#define STAGE_BYTES (2 * BM * SROW * 2)        // 20480
#define CS_STRIDE 129
#define SMEM_BYTES (BM * CS_STRIDE * 4)        // 66048

// ---------------- device scratch ----------------
__device__ __align__(16) __nv_bfloat16 g_memb[(size_t)C_ROWS * DIM]; // normalized bf16
__device__ __align__(16) __nv_bfloat16 g_xb[(size_t)B_ROWS * DIM];   // raw bf16
__device__ float g_minv[C_ROWS];
__device__ float g_xinv[B_ROWS];
__device__ __align__(16) float g_cv[(size_t)B_ROWS * CAND_PER_ROW];
__device__ __align__(16) int   g_ci[(size_t)B_ROWS * CAND_PER_ROW];

// ---------------- PTX helpers ----------------
__device__ __forceinline__ void cp16(uint32_t saddr, const void* gaddr) {
    asm volatile("cp.async.cg.shared.global [%0], [%1], 16;" :: "r"(saddr), "l"(gaddr));
}
__device__ __forceinline__ void cp_commit() {
    asm volatile("cp.async.commit_group;" ::: "memory");
}
__device__ __forceinline__ void ldsm4(uint32_t (&r)[4], uint32_t addr) {
    asm volatile("ldmatrix.sync.aligned.m8n8.x4.shared.b16 {%0,%1,%2,%3}, [%4];"
                 : "=r"(r[0]), "=r"(r[1]), "=r"(r[2]), "=r"(r[3]) : "r"(addr));
}
__device__ __forceinline__ void mma16816(float (&c)[4], const uint32_t (&a)[4],
                                         uint32_t b0, uint32_t b1) {
    asm volatile(
        "mma.sync.aligned.m16n8k16.row.col.f32.bf16.bf16.f32 "
        "{%0,%1,%2,%3},{%4,%5,%6,%7},{%8,%9},{%0,%1,%2,%3};"
        : "+f"(c[0]), "+f"(c[1]), "+f"(c[2]), "+f"(c[3])
        : "r"(a[0]), "r"(a[1]), "r"(a[2]), "r"(a[3]), "r"(b0), "r"(b1));
}

// ---------------- fused prep: warp-per-row (measured ~57us, 82-84% HBM) ----------------
__global__ __launch_bounds__(256) void prep_all_kernel(const float* __restrict__ mem,
                                                       const float* __restrict__ x) {
    const int gw = blockIdx.x * 8 + (threadIdx.x >> 5);   // global warp id
    const int lane = threadIdx.x & 31;
    const bool is_mem = (gw < C_ROWS);
    const int row = is_mem ? gw : gw - C_ROWS;
    if (!is_mem && row >= B_ROWS) return;

    const float* src = is_mem ? (mem + (size_t)row * DIM) : (x + (size_t)row * DIM);
    const float4* s4 = reinterpret_cast<const float4*>(src);

    float4 v[8];
    float ss = 0.f;
    #pragma unroll
    for (int j = 0; j < 8; j++) {
        v[j] = s4[lane + 32 * j];
        ss += v[j].x * v[j].x + v[j].y * v[j].y + v[j].z * v[j].z + v[j].w * v[j].w;
    }
    #pragma unroll
    for (int o = 16; o; o >>= 1) ss += __shfl_xor_sync(0xffffffffu, ss, o);
    float iv = 1.0f / fmaxf(sqrtf(ss), 1e-12f);
    if (lane == 0) {
        if (is_mem) g_minv[row] = iv;
        else        g_xinv[row] = iv;
    }
    float sc = is_mem ? iv : 1.0f;   // fold inv-norm into memory only (x scale rank-invariant)
    __nv_bfloat16* dst = (is_mem ? g_memb : g_xb) + (size_t)row * DIM;
    uint2* d2 = reinterpret_cast<uint2*>(dst);
    #pragma unroll
    for (int j = 0; j < 8; j++) {
        __nv_bfloat162 p0 = __floats2bfloat162_rn(v[j].x * sc, v[j].y * sc);
        __nv_bfloat162 p1 = __floats2bfloat162_rn(v[j].z * sc, v[j].w * sc);
        uint2 w;
        w.x = *reinterpret_cast<uint32_t*>(&p0);
        w.y = *reinterpret_cast<uint32_t*>(&p1);
        d2[lane + 32 * j] = w;
    }
}

// compare-exchange on (value, col) pairs, descending
#define CE(av, ac, bv, bc) do {                      \
    if ((av) < (bv)) {                               \
        float _tv = (av); (av) = (bv); (bv) = _tv;   \
        int _tc = (ac); (ac) = (bc); (bc) = _tc;     \
    }                                                \
} while (0)

// ---------------- coarse GEMM (bf16 HMMA) + 2-thread/row register top-4 ----------------
__global__ __launch_bounds__(256) void gemm_topk_kernel() {
    extern __shared__ char smem[];
    const int tid = threadIdx.x;
    const int bm = blockIdx.x;   // fast dim -> consecutive CTAs share B tile in L2
    const int bn = blockIdx.y;
    const uint32_t smem_u = (uint32_t)__cvta_generic_to_shared(smem);

    const int r0 = tid >> 2;
    const int ch = tid & 3;
    const __nv_bfloat16* gA0 = g_xb   + ((size_t)(bm * BM + r0)      * DIM + ch * 8);
    const __nv_bfloat16* gA1 = g_xb   + ((size_t)(bm * BM + r0 + 64) * DIM + ch * 8);
    const __nv_bfloat16* gB0 = g_memb + ((size_t)(bn * BN + r0)      * DIM + ch * 8);
    const __nv_bfloat16* gB1 = g_memb + ((size_t)(bn * BN + r0 + 64) * DIM + ch * 8);

    const uint32_t sa0 = (r0 * SROW + ch * 8) * 2;
    const uint32_t sa1 = ((r0 + 64) * SROW + ch * 8) * 2;

    float acc[4][4][4];
    #pragma unroll
    for (int i = 0; i < 4; i++)
        #pragma unroll
        for (int j = 0; j < 4; j++)
            #pragma unroll
            for (int q = 0; q < 4; q++) acc[i][j][q] = 0.f;

    const int lane = tid & 31;
    const int wm = ((tid >> 5) & 1) * 64;
    const int wn = (tid >> 6) * 32;

    {
        uint32_t base = smem_u;
        cp16(base + sa0, gA0);
        cp16(base + sa1, gA1);
        cp16(base + BM * SROW * 2 + sa0, gB0);
        cp16(base + BM * SROW * 2 + sa1, gB1);
        cp_commit();
    }

    const int NK = DIM / BK;  // 32
    for (int it = 0; it < NK; ++it) {
        if (it + 1 < NK) {
            uint32_t base = smem_u + ((it + 1) & 1) * STAGE_BYTES;
            size_t koff = (size_t)(it + 1) * BK;
            cp16(base + sa0, gA0 + koff);
            cp16(base + sa1, gA1 + koff);
            cp16(base + BM * SROW * 2 + sa0, gB0 + koff);
            cp16(base + BM * SROW * 2 + sa1, gB1 + koff);
            cp_commit();
            asm volatile("cp.async.wait_group 1;");
        } else {
            asm volatile("cp.async.wait_group 0;");
        }
        __syncthreads();

        uint32_t abase = smem_u + (it & 1) * STAGE_BYTES;
        uint32_t bbase = abase + BM * SROW * 2;
        #pragma unroll
        for (int kb = 0; kb < 2; ++kb) {
            uint32_t a[4][4];
            #pragma unroll
            for (int mi = 0; mi < 4; ++mi) {
                uint32_t ad = abase +
                    ((wm + mi * 16 + (lane & 15)) * SROW + kb * 16 + (lane >> 4) * 8) * 2;
                ldsm4(a[mi], ad);
            }
            uint32_t bfr[4][2];
            #pragma unroll
            for (int bp = 0; bp < 2; ++bp) {
                int mat = lane >> 3;
                uint32_t bd = bbase +
                    ((wn + bp * 16 + (mat >> 1) * 8 + (lane & 7)) * SROW +
                     kb * 16 + (mat & 1) * 8) * 2;
                uint32_t r[4];
                ldsm4(r, bd);
                bfr[bp * 2 + 0][0] = r[0]; bfr[bp * 2 + 0][1] = r[1];
                bfr[bp * 2 + 1][0] = r[2]; bfr[bp * 2 + 1][1] = r[3];
            }
            #pragma unroll
            for (int mi = 0; mi < 4; ++mi)
                #pragma unroll
                for (int ni = 0; ni < 4; ++ni)
                    mma16816(acc[mi][ni], a[mi], bfr[ni][0], bfr[ni][1]);
        }
        __syncthreads();
    }

    // epilogue: dump sims to smem
    float* Cs = reinterpret_cast<float*>(smem);
    #pragma unroll
    for (int mi = 0; mi < 4; ++mi) {
        #pragma unroll
        for (int ni = 0; ni < 4; ++ni) {
            int rb = wm + mi * 16 + (lane >> 2);
            int cb = wn + ni * 8 + (lane & 3) * 2;
            Cs[rb * CS_STRIDE + cb]             = acc[mi][ni][0];
            Cs[rb * CS_STRIDE + cb + 1]         = acc[mi][ni][1];
            Cs[(rb + 8) * CS_STRIDE + cb]       = acc[mi][ni][2];
            Cs[(rb + 8) * CS_STRIDE + cb + 1]   = acc[mi][ni][3];
        }
    }
    __syncthreads();

    // per-row top-4: 2 threads/row (64 cols each, +16 stagger for bank spread),
    // named registers only, shfl-merge of the two sorted lists
    {
        const int row = tid >> 1;
        const int h = tid & 1;
        const float* rowp = Cs + row * CS_STRIDE;
        float v0 = -1e30f, v1 = -1e30f, v2 = -1e30f, v3 = -1e30f;
        int   c0 = 0, c1 = 0, c2 = 0, c3 = 0;
        const int cofs = h << 6;       // column base 0 or 64
        const int stag = h << 4;       // +16 stagger for h=1
        #pragma unroll 4
        for (int c = 0; c < 64; ++c) {
            int col = cofs | ((c + stag) & 63);
            float v = rowp[col];
            if (v > v3) {
                if (v > v0) {
                    v3 = v2; c3 = c2; v2 = v1; c2 = c1; v1 = v0; c1 = c0; v0 = v; c0 = col;
                } else if (v > v1) {
                    v3 = v2; c3 = c2; v2 = v1; c2 = c1; v1 = v; c1 = col;
                } else if (v > v2) {
                    v3 = v2; c3 = c2; v2 = v; c2 = col;
                } else {
                    v3 = v; c3 = col;
                }
            }
        }
        // exchange partner's sorted-4 (adjacent lane), reversed elementwise max
        float o0 = __shfl_xor_sync(0xffffffffu, v0, 1);
        float o1 = __shfl_xor_sync(0xffffffffu, v1, 1);
        float o2 = __shfl_xor_sync(0xffffffffu, v2, 1);
        float o3 = __shfl_xor_sync(0xffffffffu, v3, 1);
        int   q0 = __shfl_xor_sync(0xffffffffu, c0, 1);
        int   q1 = __shfl_xor_sync(0xffffffffu, c1, 1);
        int   q2 = __shfl_xor_sync(0xffffffffu, c2, 1);
        int   q3 = __shfl_xor_sync(0xffffffffu, c3, 1);
        float m0, m1, m2, m3; int n0, n1, n2, n3;
        if (v0 >= o3) { m0 = v0; n0 = c0; } else { m0 = o3; n0 = q3; }
        if (v1 >= o2) { m1 = v1; n1 = c1; } else { m1 = o2; n1 = q2; }
        if (v2 >= o1) { m2 = v2; n2 = c2; } else { m2 = o1; n2 = q1; }
        if (v3 >= o0) { m3 = v3; n3 = c3; } else { m3 = o0; n3 = q0; }
        // bitonic resort of 4 (descending)
        CE(m0, n0, m2, n2);
        CE(m1, n1, m3, n3);
        CE(m0, n0, m1, n1);
        CE(m2, n2, m3, n3);

        if (h == 0) {
            size_t base = ((size_t)(bm * BM + row) * NTILES + bn) * CAND_PER_TILE;
            *reinterpret_cast<float4*>(&g_cv[base]) = make_float4(m0, m1, m2, m3);
            *reinterpret_cast<int4*>(&g_ci[base]) =
                make_int4(bn * BN + n0, bn * BN + n1, bn * BN + n2, bn * BN + n3);
        }
    }
}

// ---------------- phase 2: exact rescore (top-8), top-5, softmax, gather ----------------
__global__ __launch_bounds__(256) void rescore_out_kernel(const float* __restrict__ x,
                                                          const float* __restrict__ mem,
                                                          float* __restrict__ out) {
    const int row = blockIdx.x;
    const int tid = threadIdx.x, lane = tid & 31, warp = tid >> 5;
    __shared__ float sv[CAND_PER_ROW];
    __shared__ float wv[8];
    __shared__ int   wp[8];
    __shared__ int   cpos[RESCORE];
    __shared__ float ev[RESCORE];
    __shared__ int   em[RESCORE];
    __shared__ float wgt[TOPK];
    __shared__ int   sidx[TOPK];

    const float4* cv4 = reinterpret_cast<const float4*>(g_cv + (size_t)row * CAND_PER_ROW);
    float4* sv4 = reinterpret_cast<float4*>(sv);
    for (int j = tid; j < CAND_PER_ROW / 4; j += 256) sv4[j] = cv4[j];
    __syncthreads();

    // approx top-8 by coarse score (iterative extract-max; margin >> bf16 noise)
    for (int i = 0; i < RESCORE; ++i) {
        float best = -1e30f; int bp = -1;
        for (int j = tid; j < CAND_PER_ROW; j += 256) {
            float v = sv[j];
            if (v > best) { best = v; bp = j; }
        }
        #pragma unroll
        for (int o = 16; o; o >>= 1) {
            float ov = __shfl_down_sync(0xffffffffu, best, o);
            int   op = __shfl_down_sync(0xffffffffu, bp, o);
            if (ov > best) { best = ov; bp = op; }
        }
        if (lane == 0) { wv[warp] = best; wp[warp] = bp; }
        __syncthreads();
        if (tid == 0) {
            float bb = wv[0]; int pp = wp[0];
            #pragma unroll
            for (int w2 = 1; w2 < 8; w2++) if (wv[w2] > bb) { bb = wv[w2]; pp = wp[w2]; }
            cpos[i] = pp;
            sv[pp] = -1e30f;
        }
        __syncthreads();
    }

    // exact fp32 rescore of 8 candidates (1 per warp)
    const float4* xr = reinterpret_cast<const float4*>(x + (size_t)row * DIM);
    {
        int i = warp;
        int mi = g_ci[(size_t)row * CAND_PER_ROW + cpos[i]];
        const float4* mr = reinterpret_cast<const float4*>(mem + (size_t)mi * DIM);
        float s = 0.f;
        #pragma unroll
        for (int j = 0; j < 8; j++) {
            float4 a = xr[lane + 32 * j], b = mr[lane + 32 * j];
            s += a.x * b.x + a.y * b.y + a.z * b.z + a.w * b.w;
        }
        #pragma unroll
        for (int o = 16; o; o >>= 1) s += __shfl_down_sync(0xffffffffu, s, o);
        if (lane == 0) { ev[i] = s * g_minv[mi] * g_xinv[row]; em[i] = mi; }
    }
    __syncthreads();

    if (tid == 0) {
        bool used[RESCORE];
        #pragma unroll
        for (int i = 0; i < RESCORE; i++) used[i] = false;
        float tv[TOPK]; int ti[TOPK];
        #pragma unroll
        for (int r = 0; r < TOPK; ++r) {
            float bb = -1e30f; int pp = 0;
            for (int i = 0; i < RESCORE; i++)
                if (!used[i] && ev[i] > bb) { bb = ev[i]; pp = i; }
            used[pp] = true; tv[r] = bb; ti[r] = pp;
        }
        float mx = tv[0];
        float e[TOPK], se = 0.f;
        #pragma unroll
        for (int i = 0; i < TOPK; i++) { e[i] = expf(tv[i] - mx); se += e[i]; }
        #pragma unroll
        for (int i = 0; i < TOPK; i++) { wgt[i] = e[i] / se; sidx[i] = em[ti[i]]; }
    }
    __syncthreads();

    // weighted gather of raw memory rows
    float4 accv = make_float4(0.f, 0.f, 0.f, 0.f);
    #pragma unroll
    for (int i = 0; i < TOPK; i++) {
        const float4* mr = reinterpret_cast<const float4*>(mem + (size_t)sidx[i] * DIM);
        float4 m = mr[tid];
        float wg = wgt[i];
        accv.x += wg * m.x; accv.y += wg * m.y; accv.z += wg * m.z; accv.w += wg * m.w;
    }
    reinterpret_cast<float4*>(out + (size_t)row * DIM)[tid] = accv;
}

// ---------------- launch ----------------
extern "C" void kernel_launch(void* const* d_in, const int* in_sizes, int n_in,
                              void* d_out, int out_size) {
    const float* x   = (const float*)d_in[0];
    const float* mem = (const float*)d_in[1];
    float* out = (float*)d_out;

    cudaFuncSetAttribute(gemm_topk_kernel,
                         cudaFuncAttributeMaxDynamicSharedMemorySize, SMEM_BYTES);

    prep_all_kernel<<<(C_ROWS + B_ROWS) / 8, 256>>>(mem, x);
    gemm_topk_kernel<<<dim3(B_ROWS / BM, NTILES), 256, SMEM_BYTES>>>();
    rescore_out_kernel<<<B_ROWS, 256>>>(x, mem, out);
}